// round 13
// baseline (speedup 1.0000x reference)
#include <cuda_runtime.h>
#include <cuda_bf16.h>
#include <math_constants.h>
#include <cstdint>

// Problem constants (fixed by setup_inputs)
#define D_MODEL 1024
#define NHEAD   16
#define HDIM    64
#define KCAT    3072          // 3 * D_MODEL (bf16-split: A=[hi,hi,lo], W=[hi,lo,hi])

// ---------------- scratch (no allocations allowed) ----------------
__device__ __nv_bfloat16 g_Xcat[4096 * KCAT];
__device__ __nv_bfloat16 g_Wcat[4096 * KCAT];   // 4 weights stacked (q,k,v,o)
__device__ __nv_bfloat16 g_Ocat[4096 * KCAT];   // attention out, split-cat [hi,hi,lo]
__device__ __nv_bfloat16 g_Qh[4096 * 1024], g_Ql[4096 * 1024];
__device__ __nv_bfloat16 g_Kh[4096 * 1024], g_Kl[4096 * 1024];
__device__ __nv_bfloat16 g_Vh[4096 * 1024], g_Vl[4096 * 1024];

// =================== small PTX helpers (plain sm_80/90 features only) ===================
__device__ __forceinline__ uint32_t smem_u32(const void* p) {
    uint32_t a;
    asm("{ .reg .u64 t; cvta.to.shared.u64 t, %1; cvt.u32.u64 %0, t; }" : "=r"(a) : "l"(p));
    return a;
}
__device__ __forceinline__ void cp16(uint32_t dst, const void* src) {
    asm volatile("cp.async.cg.shared.global [%0], [%1], 16;" :: "r"(dst), "l"(src) : "memory");
}
__device__ __forceinline__ void ldm_x4(uint32_t* r, uint32_t addr) {
    asm volatile("ldmatrix.sync.aligned.m8n8.x4.shared.b16 {%0,%1,%2,%3}, [%4];"
                 : "=r"(r[0]), "=r"(r[1]), "=r"(r[2]), "=r"(r[3]) : "r"(addr));
}
__device__ __forceinline__ void ldm_x4_t(uint32_t* r, uint32_t addr) {
    asm volatile("ldmatrix.sync.aligned.m8n8.x4.trans.shared.b16 {%0,%1,%2,%3}, [%4];"
                 : "=r"(r[0]), "=r"(r[1]), "=r"(r[2]), "=r"(r[3]) : "r"(addr));
}
__device__ __forceinline__ void mma16816(float* d, const uint32_t* a, const uint32_t* b) {
    asm volatile(
        "mma.sync.aligned.m16n8k16.row.col.f32.bf16.bf16.f32 "
        "{%0,%1,%2,%3}, {%4,%5,%6,%7}, {%8,%9}, {%0,%1,%2,%3};"
        : "+f"(d[0]), "+f"(d[1]), "+f"(d[2]), "+f"(d[3])
        : "r"(a[0]), "r"(a[1]), "r"(a[2]), "r"(a[3]), "r"(b[0]), "r"(b[1]));
}
__device__ __forceinline__ uint32_t pk2(__nv_bfloat16 a, __nv_bfloat16 b) {
    return (uint32_t)__bfloat16_as_ushort(a) | ((uint32_t)__bfloat16_as_ushort(b) << 16);
}
__device__ __forceinline__ void split2(float a, float b, uint32_t& hp, uint32_t& lp) {
    __nv_bfloat16 ha = __float2bfloat16(a), hb = __float2bfloat16(b);
    __nv_bfloat16 la = __float2bfloat16(a - __bfloat162float(ha));
    __nv_bfloat16 lb = __float2bfloat16(b - __bfloat162float(hb));
    hp = pk2(ha, hb); lp = pk2(la, lb);
}

// =================== fp32 -> bf16 hi/lo split-cat conversion ===================
__device__ __forceinline__ void conv_body(
    const float* __restrict__ src, __nv_bfloat16* __restrict__ dst, int mode, int i4)
{
    float4 v = ((const float4*)src)[i4];
    int row = i4 >> 8;
    int c   = (i4 & 255) * 4;
    float f[4] = {v.x, v.y, v.z, v.w};
    __nv_bfloat16 h[4], l[4];
#pragma unroll
    for (int i = 0; i < 4; i++) {
        h[i] = __float2bfloat16(f[i]);
        l[i] = __float2bfloat16(f[i] - __bfloat162float(h[i]));
    }
    uint2 hp = make_uint2(pk2(h[0], h[1]), pk2(h[2], h[3]));
    uint2 lp = make_uint2(pk2(l[0], l[1]), pk2(l[2], l[3]));
    size_t b = (size_t)row * KCAT + c;
    *(uint2*)&dst[b]        = hp;
    *(uint2*)&dst[b + 1024] = mode ? lp : hp;
    *(uint2*)&dst[b + 2048] = mode ? hp : lp;
}
__global__ __launch_bounds__(256) void convert_split(
    const float* __restrict__ src, __nv_bfloat16* __restrict__ dst, int mode)
{
    conv_body(src, dst, mode, blockIdx.x * blockDim.x + threadIdx.x);
}
// all four weights in one launch: grid (1024, 4)
__global__ __launch_bounds__(256) void convert_w4(
    const float* __restrict__ W0, const float* __restrict__ W1,
    const float* __restrict__ W2, const float* __restrict__ W3,
    __nv_bfloat16* __restrict__ dst)
{
    int w = blockIdx.y;
    const float* src = (w == 0) ? W0 : (w == 1) ? W1 : (w == 2) ? W2 : W3;
    conv_body(src, dst + (size_t)w * 1024 * KCAT, 1, blockIdx.x * blockDim.x + threadIdx.x);
}

// =================== mma.sync bf16 GEMM: C[M,1024] = A_cat[M,3072] @ W_cat^T ===================
// Block tile 256x128, BK=32, 256 threads = 8 warps (4m x 2n), warp tile 64x64.
// Double-buffered cp.async, dynamic smem. Rows padded to 40 bf16 (80B) -> conflict-free ldmatrix.
#define BK       32
#define ASTR     40
#define GA_BYTES (256 * ASTR * 2)                  // 20480
#define GB_BYTES (128 * ASTR * 2)                  // 10240
#define GSTG     (GA_BYTES + GB_BYTES)             // 30720
#define GEMM_SMEM (2 * GSTG)                       // 61440

__global__ __launch_bounds__(256, 1) void gemm_mma(
    const __nv_bfloat16* __restrict__ A, const __nv_bfloat16* __restrict__ W,
    int wbase, int mode, float* __restrict__ Cf,
    __nv_bfloat16* __restrict__ H0, __nv_bfloat16* __restrict__ L0,
    __nv_bfloat16* __restrict__ H1, __nv_bfloat16* __restrict__ L1,
    __nv_bfloat16* __restrict__ H2, __nv_bfloat16* __restrict__ L2)
{
    extern __shared__ __nv_bfloat16 gsm[];
    const uint32_t sb = smem_u32(gsm);

    const int z  = blockIdx.z;
    const int m0 = blockIdx.y * 256;
    const int n0 = blockIdx.x * 128;
    const int wrow0 = wbase + z * 1024 + n0;

    const int t    = threadIdx.x;
    const int lane = t & 31;
    const int wid  = t >> 5;
    const int wm   = wid & 3;          // 4 warps down: 64 rows each
    const int wn   = wid >> 2;         // 2 warps across: 64 cols each

    float acc[4][8][4];
#pragma unroll
    for (int mt = 0; mt < 4; mt++)
#pragma unroll
        for (int nt = 0; nt < 8; nt++)
#pragma unroll
            for (int q = 0; q < 4; q++) acc[mt][nt][q] = 0.f;

    const int nk = KCAT / BK;          // 96

    // ---- stage 0 prologue ----
    {
#pragma unroll
        for (int i = 0; i < 4; i++) {
            int ci = t + 256 * i;                    // A: 1024 chunks (256 rows x 4)
            int row = ci >> 2, col8 = (ci & 3) * 8;
            cp16(sb + (uint32_t)(row * ASTR + col8) * 2, A + (size_t)(m0 + row) * KCAT + col8);
        }
#pragma unroll
        for (int i = 0; i < 2; i++) {
            int ci = t + 256 * i;                    // B: 512 chunks (128 rows x 4)
            int row = ci >> 2, col8 = (ci & 3) * 8;
            cp16(sb + GA_BYTES + (uint32_t)(row * ASTR + col8) * 2,
                 W + (size_t)(wrow0 + row) * KCAT + col8);
        }
        asm volatile("cp.async.commit_group;" ::: "memory");
    }

    for (int k = 0; k < nk; k++) {
        const int s = k & 1;
        if (k + 1 < nk) {
            const int sn = (k + 1) & 1;
            const int kof = (k + 1) * BK;
            const uint32_t so = (uint32_t)(sn * GSTG);
#pragma unroll
            for (int i = 0; i < 4; i++) {
                int ci = t + 256 * i;
                int row = ci >> 2, col8 = (ci & 3) * 8;
                cp16(sb + so + (uint32_t)(row * ASTR + col8) * 2,
                     A + (size_t)(m0 + row) * KCAT + kof + col8);
            }
#pragma unroll
            for (int i = 0; i < 2; i++) {
                int ci = t + 256 * i;
                int row = ci >> 2, col8 = (ci & 3) * 8;
                cp16(sb + so + GA_BYTES + (uint32_t)(row * ASTR + col8) * 2,
                     W + (size_t)(wrow0 + row) * KCAT + kof + col8);
            }
            asm volatile("cp.async.commit_group;" ::: "memory");
            asm volatile("cp.async.wait_group 1;" ::: "memory");
        } else {
            asm volatile("cp.async.wait_group 0;" ::: "memory");
        }
        __syncthreads();

        const uint32_t abase = sb + (uint32_t)(s * GSTG);
        const uint32_t bbase = abase + GA_BYTES;
#pragma unroll
        for (int kk = 0; kk < BK; kk += 16) {
            uint32_t af[4][4];
#pragma unroll
            for (int mt = 0; mt < 4; mt++) {
                int row = wm * 64 + mt * 16 + (lane & 15);
                int col = kk + (lane >> 4) * 8;
                ldm_x4(af[mt], abase + (uint32_t)(row * ASTR + col) * 2);
            }
            uint32_t bf[8][2];
#pragma unroll
            for (int np = 0; np < 4; np++) {
                int nrow = wn * 64 + np * 16 + ((lane >> 4) << 3) + (lane & 7);
                int kcol = kk + ((lane >> 3) & 1) * 8;
                uint32_t r[4];
                ldm_x4(r, bbase + (uint32_t)(nrow * ASTR + kcol) * 2);
                bf[np * 2 + 0][0] = r[0]; bf[np * 2 + 0][1] = r[1];
                bf[np * 2 + 1][0] = r[2]; bf[np * 2 + 1][1] = r[3];
            }
#pragma unroll
            for (int mt = 0; mt < 4; mt++)
#pragma unroll
                for (int nt = 0; nt < 8; nt++)
                    mma16816(acc[mt][nt], af[mt], bf[nt]);
        }
        __syncthreads();
    }

    if (mode == 0) {
#pragma unroll
        for (int mt = 0; mt < 4; mt++) {
            int row = m0 + wm * 64 + mt * 16 + (lane >> 2);
#pragma unroll
            for (int nt = 0; nt < 8; nt++) {
                int col = n0 + wn * 64 + nt * 8 + (lane & 3) * 2;
                *(float2*)&Cf[(size_t)row * 1024 + col]       = make_float2(acc[mt][nt][0], acc[mt][nt][1]);
                *(float2*)&Cf[(size_t)(row + 8) * 1024 + col] = make_float2(acc[mt][nt][2], acc[mt][nt][3]);
            }
        }
    } else {
        __nv_bfloat16* Ch = (z == 0) ? H0 : (z == 1) ? H1 : H2;
        __nv_bfloat16* Cl = (z == 0) ? L0 : (z == 1) ? L1 : L2;
        const float sc = (z == 0) ? 0.125f : 1.0f;   // fold 1/sqrt(Hd) into Q
#pragma unroll
        for (int mt = 0; mt < 4; mt++) {
            int row = m0 + wm * 64 + mt * 16 + (lane >> 2);
#pragma unroll
            for (int nt = 0; nt < 8; nt++) {
                int col = n0 + wn * 64 + nt * 8 + (lane & 3) * 2;
                uint32_t hp, lp;
                split2(acc[mt][nt][0] * sc, acc[mt][nt][1] * sc, hp, lp);
                *(uint32_t*)&Ch[(size_t)row * 1024 + col] = hp;
                *(uint32_t*)&Cl[(size_t)row * 1024 + col] = lp;
                split2(acc[mt][nt][2] * sc, acc[mt][nt][3] * sc, hp, lp);
                *(uint32_t*)&Ch[(size_t)(row + 8) * 1024 + col] = hp;
                *(uint32_t*)&Cl[(size_t)(row + 8) * 1024 + col] = lp;
            }
        }
    }
}

// =================== Flash attention v3: mma.sync bf16 3-split ===================
// Block: 128 q-rows x 64 k-tile, 256 threads = 8 warps (m16 each).
// Q fragments hoisted out of the k-loop (register-resident).
#define FSTR3 72
#define QH_OFF 0
#define QL_OFF (128 * FSTR3)
#define ST_OFF(s) (2 * 128 * FSTR3 + (s) * (4 * 64 * FSTR3))
#define KH_OFF 0
#define KL_OFF (64 * FSTR3)
#define VH_OFF (2 * 64 * FSTR3)
#define VL_OFF (3 * 64 * FSTR3)
#define FLASH3_SMEM ((2 * 128 * FSTR3 + 2 * 4 * 64 * FSTR3) * 2)   // 110,592 B

__global__ __launch_bounds__(256) void flash_fwd3(
    const __nv_bfloat16* __restrict__ Qh, const __nv_bfloat16* __restrict__ Ql,
    const __nv_bfloat16* __restrict__ Kh, const __nv_bfloat16* __restrict__ Kl,
    const __nv_bfloat16* __restrict__ Vh, const __nv_bfloat16* __restrict__ Vl,
    __nv_bfloat16* __restrict__ Ocat, const int* __restrict__ causalp, int S)
{
    extern __shared__ __nv_bfloat16 smem3[];
    const uint32_t sb = smem_u32(smem3);

    const int qt = gridDim.x - 1 - blockIdx.x;   // heavy (large-qt) blocks first
    const int h  = blockIdx.y;
    const int b  = blockIdx.z;
    const int t  = threadIdx.x;
    const int lane = t & 31;
    const int wid  = t >> 5;
    const int wq   = wid * 16;
    const int causal = causalp[0];

    const int q0 = qt * 128;
    const size_t tok0 = (size_t)b * S;
    const size_t colh = (size_t)h * HDIM;

    // ---- prologue: Q tiles (own commit group), then k-tile 0 ----
#pragma unroll
    for (int c = 0; c < 4; c++) {
        int ci = t + 256 * c;            // 0..1023 chunks of 8 bf16
        int row = ci >> 3, col8 = (ci & 7) * 8;
        const __nv_bfloat16* gq = Qh + (tok0 + q0 + row) * D_MODEL + colh + col8;
        const __nv_bfloat16* gl = Ql + (tok0 + q0 + row) * D_MODEL + colh + col8;
        cp16(sb + (uint32_t)(QH_OFF + row * FSTR3 + col8) * 2, gq);
        cp16(sb + (uint32_t)(QL_OFF + row * FSTR3 + col8) * 2, gl);
    }
    asm volatile("cp.async.commit_group;" ::: "memory");
    const int ntot = S >> 6;
    const int nkt  = causal ? min(ntot, 2 * qt + 2) : ntot;
    {
#pragma unroll
        for (int c = 0; c < 2; c++) {
            int ci = t + 256 * c;        // 0..511
            int row = ci >> 3, col8 = (ci & 7) * 8;
            size_t g = (tok0 + row) * D_MODEL + colh + col8;
            uint32_t d = (uint32_t)(ST_OFF(0) + row * FSTR3 + col8) * 2;
            cp16(sb + d + KH_OFF * 2, Kh + g);
            cp16(sb + d + KL_OFF * 2, Kl + g);
            cp16(sb + d + VH_OFF * 2, Vh + g);
            cp16(sb + d + VL_OFF * 2, Vl + g);
        }
        asm volatile("cp.async.commit_group;" ::: "memory");
    }

    // ---- Q fragments: register-resident for the whole k-loop ----
    asm volatile("cp.async.wait_group 1;" ::: "memory");   // Q group complete
    __syncthreads();
    uint32_t qfh[4][4], qfl[4][4];
#pragma unroll
    for (int kk4 = 0; kk4 < 4; kk4++) {
        int row = wq + (lane & 15);
        int col = kk4 * 16 + (lane >> 4) * 8;
        ldm_x4(qfh[kk4], sb + (uint32_t)(QH_OFF + row * FSTR3 + col) * 2);
        ldm_x4(qfl[kk4], sb + (uint32_t)(QL_OFF + row * FSTR3 + col) * 2);
    }

    float sacc[8][4], oacc[8][4];
#pragma unroll
    for (int nt = 0; nt < 8; nt++)
#pragma unroll
        for (int q = 0; q < 4; q++) oacc[nt][q] = 0.f;
    float mrun0 = -CUDART_INF_F, mrun1 = -CUDART_INF_F, lrun0 = 0.f, lrun1 = 0.f;

    for (int kt = 0; kt < nkt; kt++) {
        const int s  = kt & 1;
        const int k0 = kt * 64;
        if (kt + 1 < nkt) {
            const int sn = (kt + 1) & 1;
#pragma unroll
            for (int c = 0; c < 2; c++) {
                int ci = t + 256 * c;
                int row = ci >> 3, col8 = (ci & 7) * 8;
                size_t g = (tok0 + k0 + 64 + row) * D_MODEL + colh + col8;
                uint32_t d = (uint32_t)(ST_OFF(sn) + row * FSTR3 + col8) * 2;
                cp16(sb + d + KH_OFF * 2, Kh + g);
                cp16(sb + d + KL_OFF * 2, Kl + g);
                cp16(sb + d + VH_OFF * 2, Vh + g);
                cp16(sb + d + VL_OFF * 2, Vl + g);
            }
            asm volatile("cp.async.commit_group;" ::: "memory");
            asm volatile("cp.async.wait_group 1;" ::: "memory");
        } else {
            asm volatile("cp.async.wait_group 0;" ::: "memory");
        }
        __syncthreads();

        const uint32_t kbase = sb + (uint32_t)ST_OFF(s) * 2;

        // ---- S = Q K^T (3-term split), per warp 16q x 64k ----
#pragma unroll
        for (int nt = 0; nt < 8; nt++)
#pragma unroll
            for (int q = 0; q < 4; q++) sacc[nt][q] = 0.f;

#pragma unroll
        for (int kk4 = 0; kk4 < 4; kk4++) {
            const int kk = kk4 * 16;
            uint32_t bh[8][2], bl[8][2];
#pragma unroll
            for (int np = 0; np < 4; np++) {
                int nrow = np * 16 + ((lane >> 4) << 3) + (lane & 7);
                int kcol = kk + ((lane >> 3) & 1) * 8;
                uint32_t r[4];
                ldm_x4(r, kbase + (uint32_t)(KH_OFF + nrow * FSTR3 + kcol) * 2);
                bh[np * 2 + 0][0] = r[0]; bh[np * 2 + 0][1] = r[1];
                bh[np * 2 + 1][0] = r[2]; bh[np * 2 + 1][1] = r[3];
                ldm_x4(r, kbase + (uint32_t)(KL_OFF + nrow * FSTR3 + kcol) * 2);
                bl[np * 2 + 0][0] = r[0]; bl[np * 2 + 0][1] = r[1];
                bl[np * 2 + 1][0] = r[2]; bl[np * 2 + 1][1] = r[3];
            }
#pragma unroll
            for (int nt = 0; nt < 8; nt++) {
                mma16816(sacc[nt], qfh[kk4], bh[nt]);
                mma16816(sacc[nt], qfh[kk4], bl[nt]);
                mma16816(sacc[nt], qfl[kk4], bh[nt]);
            }
        }

        // ---- causal mask ----
        if (causal && (k0 + 63 > q0 + wq)) {
            int qg0 = q0 + wq + (lane >> 2);
#pragma unroll
            for (int nt = 0; nt < 8; nt++) {
                int kg = k0 + nt * 8 + (lane & 3) * 2;
                if (kg     > qg0)     sacc[nt][0] = -CUDART_INF_F;
                if (kg + 1 > qg0)     sacc[nt][1] = -CUDART_INF_F;
                if (kg     > qg0 + 8) sacc[nt][2] = -CUDART_INF_F;
                if (kg + 1 > qg0 + 8) sacc[nt][3] = -CUDART_INF_F;
            }
        }

        // ---- online softmax (rows r0 = lane>>2, r1 = r0+8; quad = 4 lanes/row) ----
        {
            float m0 = sacc[0][0], m1 = sacc[0][2];
#pragma unroll
            for (int nt = 0; nt < 8; nt++) {
                m0 = fmaxf(m0, fmaxf(sacc[nt][0], sacc[nt][1]));
                m1 = fmaxf(m1, fmaxf(sacc[nt][2], sacc[nt][3]));
            }
            m0 = fmaxf(m0, __shfl_xor_sync(0xffffffffu, m0, 1));
            m0 = fmaxf(m0, __shfl_xor_sync(0xffffffffu, m0, 2));
            m1 = fmaxf(m1, __shfl_xor_sync(0xffffffffu, m1, 1));
            m1 = fmaxf(m1, __shfl_xor_sync(0xffffffffu, m1, 2));
            float mn0 = fmaxf(mrun0, m0), mn1 = fmaxf(mrun1, m1);
            float cr0 = __expf(mrun0 - mn0), cr1 = __expf(mrun1 - mn1);
            float ls0 = 0.f, ls1 = 0.f;
#pragma unroll
            for (int nt = 0; nt < 8; nt++) {
                sacc[nt][0] = __expf(sacc[nt][0] - mn0);
                sacc[nt][1] = __expf(sacc[nt][1] - mn0);
                sacc[nt][2] = __expf(sacc[nt][2] - mn1);
                sacc[nt][3] = __expf(sacc[nt][3] - mn1);
                ls0 += sacc[nt][0] + sacc[nt][1];
                ls1 += sacc[nt][2] + sacc[nt][3];
            }
            ls0 += __shfl_xor_sync(0xffffffffu, ls0, 1);
            ls0 += __shfl_xor_sync(0xffffffffu, ls0, 2);
            ls1 += __shfl_xor_sync(0xffffffffu, ls1, 1);
            ls1 += __shfl_xor_sync(0xffffffffu, ls1, 2);
            lrun0 = lrun0 * cr0 + ls0;  mrun0 = mn0;
            lrun1 = lrun1 * cr1 + ls1;  mrun1 = mn1;
#pragma unroll
            for (int nt = 0; nt < 8; nt++) {
                oacc[nt][0] *= cr0; oacc[nt][1] *= cr0;
                oacc[nt][2] *= cr1; oacc[nt][3] *= cr1;
            }
        }

        // ---- O += P V (3-term split); P frags direct from sacc ----
#pragma unroll
        for (int jt = 0; jt < 4; jt++) {
            uint32_t aPh[4], aPl[4];
            split2(sacc[2 * jt][0],     sacc[2 * jt][1],     aPh[0], aPl[0]);
            split2(sacc[2 * jt][2],     sacc[2 * jt][3],     aPh[1], aPl[1]);
            split2(sacc[2 * jt + 1][0], sacc[2 * jt + 1][1], aPh[2], aPl[2]);
            split2(sacc[2 * jt + 1][2], sacc[2 * jt + 1][3], aPh[3], aPl[3]);

            uint32_t vh[8][2], vl[8][2];
#pragma unroll
            for (int dp = 0; dp < 4; dp++) {
                int vrow = jt * 16 + (lane & 15);
                int vcol = dp * 16 + (lane >> 4) * 8;
                uint32_t r[4];
                ldm_x4_t(r, kbase + (uint32_t)(VH_OFF + vrow * FSTR3 + vcol) * 2);
                vh[dp * 2 + 0][0] = r[0]; vh[dp * 2 + 0][1] = r[1];
                vh[dp * 2 + 1][0] = r[2]; vh[dp * 2 + 1][1] = r[3];
                ldm_x4_t(r, kbase + (uint32_t)(VL_OFF + vrow * FSTR3 + vcol) * 2);
                vl[dp * 2 + 0][0] = r[0]; vl[dp * 2 + 0][1] = r[1];
                vl[dp * 2 + 1][0] = r[2]; vl[dp * 2 + 1][1] = r[3];
            }
#pragma unroll
            for (int nt = 0; nt < 8; nt++) {
                mma16816(oacc[nt], aPh, vh[nt]);
                mma16816(oacc[nt], aPh, vl[nt]);
                mma16816(oacc[nt], aPl, vh[nt]);
            }
        }
        __syncthreads();
    }

    // ---- epilogue: normalize, write split-cat [hi,hi,lo] into Ocat ----
    {
        float inv0 = 1.f / lrun0, inv1 = 1.f / lrun1;
        size_t r0 = tok0 + q0 + wq + (lane >> 2);
        size_t r1 = r0 + 8;
#pragma unroll
        for (int nt = 0; nt < 8; nt++) {
            size_t col = colh + nt * 8 + (lane & 3) * 2;
            uint32_t hp, lp;
            split2(oacc[nt][0] * inv0, oacc[nt][1] * inv0, hp, lp);
            *(uint32_t*)&Ocat[r0 * KCAT + col]        = hp;
            *(uint32_t*)&Ocat[r0 * KCAT + col + 1024] = hp;
            *(uint32_t*)&Ocat[r0 * KCAT + col + 2048] = lp;
            split2(oacc[nt][2] * inv1, oacc[nt][3] * inv1, hp, lp);
            *(uint32_t*)&Ocat[r1 * KCAT + col]        = hp;
            *(uint32_t*)&Ocat[r1 * KCAT + col + 1024] = hp;
            *(uint32_t*)&Ocat[r1 * KCAT + col + 2048] = lp;
        }
    }
}

// ---------------- launch ----------------
extern "C" void kernel_launch(void* const* d_in, const int* in_sizes, int n_in,
                              void* d_out, int out_size)
{
    const float* x  = (const float*)d_in[0];
    const float* Wq = (const float*)d_in[1];
    const float* Wk = (const float*)d_in[2];
    const float* Wv = (const float*)d_in[3];
    const float* Wo = (const float*)d_in[4];
    const int*   causal = (const int*)d_in[5];

    const int BS = in_sizes[0] / D_MODEL;   // 4096
    const int S  = 2048;
    const int B  = BS / S;

    __nv_bfloat16 *xcat, *wcat, *ocat, *qh, *ql, *kh, *kl, *vh, *vl;
    cudaGetSymbolAddress((void**)&xcat, g_Xcat);
    cudaGetSymbolAddress((void**)&wcat, g_Wcat);
    cudaGetSymbolAddress((void**)&ocat, g_Ocat);
    cudaGetSymbolAddress((void**)&qh, g_Qh);  cudaGetSymbolAddress((void**)&ql, g_Ql);
    cudaGetSymbolAddress((void**)&kh, g_Kh);  cudaGetSymbolAddress((void**)&kl, g_Kl);
    cudaGetSymbolAddress((void**)&vh, g_Vh);  cudaGetSymbolAddress((void**)&vl, g_Vl);

    cudaFuncSetAttribute(gemm_mma, cudaFuncAttributeMaxDynamicSharedMemorySize, GEMM_SMEM);
    cudaFuncSetAttribute(flash_fwd3, cudaFuncAttributeMaxDynamicSharedMemorySize, FLASH3_SMEM);

    // ---- convert x and all four weights to bf16 split-cat ----
    convert_split<<<(BS * 256) / 256, 256>>>(x, xcat, 0);
    convert_w4<<<dim3(1024, 4), 256>>>(Wq, Wk, Wv, Wo, wcat);

    // ---- Q/K/V projections -> bf16 hi/lo split outputs (Q pre-scaled by 0.125) ----
    gemm_mma<<<dim3(D_MODEL / 128, BS / 256, 3), 256, GEMM_SMEM>>>(
        xcat, wcat, 0, 1, nullptr, qh, ql, kh, kl, vh, vl);

    // ---- tensor-core flash attention -> Ocat (split-cat) ----
    dim3 gfl(S / 128, NHEAD, B);
    flash_fwd3<<<gfl, 256, FLASH3_SMEM>>>(qh, ql, kh, kl, vh, vl, ocat, causal, S);

    // ---- output projection -> fp32 d_out ----
    gemm_mma<<<dim3(D_MODEL / 128, BS / 256, 1), 256, GEMM_SMEM>>>(
        ocat, wcat, 3 * 1024, 0, (float*)d_out,
        nullptr, nullptr, nullptr, nullptr, nullptr, nullptr);
}

// round 17
// speedup vs baseline: 1.0301x; 1.0301x over previous
#include <cuda_runtime.h>
#include <cuda_bf16.h>
#include <math_constants.h>
#include <cstdint>

// Problem constants (fixed by setup_inputs)
#define D_MODEL 1024
#define NHEAD   16
#define HDIM    64
#define KCAT    3072          // 3 * D_MODEL (bf16-split: A=[hi,hi,lo], W=[hi,lo,hi])

// ---------------- scratch (no allocations allowed) ----------------
__device__ __nv_bfloat16 g_Xcat[4096 * KCAT];
__device__ __nv_bfloat16 g_Wcat[4096 * KCAT];   // 4 weights stacked (q,k,v,o)
__device__ __nv_bfloat16 g_Ocat[4096 * KCAT];   // attention out, split-cat [hi,hi,lo]
__device__ __nv_bfloat16 g_Qh[4096 * 1024], g_Ql[4096 * 1024];
__device__ __nv_bfloat16 g_Kh[4096 * 1024], g_Kl[4096 * 1024];
__device__ __nv_bfloat16 g_Vh[4096 * 1024], g_Vl[4096 * 1024];

// =================== small PTX helpers (plain sm_80/90 features only) ===================
__device__ __forceinline__ uint32_t smem_u32(const void* p) {
    uint32_t a;
    asm("{ .reg .u64 t; cvta.to.shared.u64 t, %1; cvt.u32.u64 %0, t; }" : "=r"(a) : "l"(p));
    return a;
}
__device__ __forceinline__ void cp16(uint32_t dst, const void* src) {
    asm volatile("cp.async.cg.shared.global [%0], [%1], 16;" :: "r"(dst), "l"(src) : "memory");
}
__device__ __forceinline__ void ldm_x4(uint32_t* r, uint32_t addr) {
    asm volatile("ldmatrix.sync.aligned.m8n8.x4.shared.b16 {%0,%1,%2,%3}, [%4];"
                 : "=r"(r[0]), "=r"(r[1]), "=r"(r[2]), "=r"(r[3]) : "r"(addr));
}
__device__ __forceinline__ void ldm_x4_t(uint32_t* r, uint32_t addr) {
    asm volatile("ldmatrix.sync.aligned.m8n8.x4.trans.shared.b16 {%0,%1,%2,%3}, [%4];"
                 : "=r"(r[0]), "=r"(r[1]), "=r"(r[2]), "=r"(r[3]) : "r"(addr));
}
__device__ __forceinline__ void mma16816(float* d, const uint32_t* a, const uint32_t* b) {
    asm volatile(
        "mma.sync.aligned.m16n8k16.row.col.f32.bf16.bf16.f32 "
        "{%0,%1,%2,%3}, {%4,%5,%6,%7}, {%8,%9}, {%0,%1,%2,%3};"
        : "+f"(d[0]), "+f"(d[1]), "+f"(d[2]), "+f"(d[3])
        : "r"(a[0]), "r"(a[1]), "r"(a[2]), "r"(a[3]), "r"(b[0]), "r"(b[1]));
}
__device__ __forceinline__ uint32_t pk2(__nv_bfloat16 a, __nv_bfloat16 b) {
    return (uint32_t)__bfloat16_as_ushort(a) | ((uint32_t)__bfloat16_as_ushort(b) << 16);
}
__device__ __forceinline__ void split2(float a, float b, uint32_t& hp, uint32_t& lp) {
    __nv_bfloat16 ha = __float2bfloat16(a), hb = __float2bfloat16(b);
    __nv_bfloat16 la = __float2bfloat16(a - __bfloat162float(ha));
    __nv_bfloat16 lb = __float2bfloat16(b - __bfloat162float(hb));
    hp = pk2(ha, hb); lp = pk2(la, lb);
}

// =================== fp32 -> bf16 hi/lo split-cat conversion ===================
__device__ __forceinline__ void conv_body(
    const float* __restrict__ src, __nv_bfloat16* __restrict__ dst, int mode, int i4)
{
    float4 v = ((const float4*)src)[i4];
    int row = i4 >> 8;
    int c   = (i4 & 255) * 4;
    float f[4] = {v.x, v.y, v.z, v.w};
    __nv_bfloat16 h[4], l[4];
#pragma unroll
    for (int i = 0; i < 4; i++) {
        h[i] = __float2bfloat16(f[i]);
        l[i] = __float2bfloat16(f[i] - __bfloat162float(h[i]));
    }
    uint2 hp = make_uint2(pk2(h[0], h[1]), pk2(h[2], h[3]));
    uint2 lp = make_uint2(pk2(l[0], l[1]), pk2(l[2], l[3]));
    size_t b = (size_t)row * KCAT + c;
    *(uint2*)&dst[b]        = hp;
    *(uint2*)&dst[b + 1024] = mode ? lp : hp;
    *(uint2*)&dst[b + 2048] = mode ? hp : lp;
}
__global__ __launch_bounds__(256) void convert_split(
    const float* __restrict__ src, __nv_bfloat16* __restrict__ dst, int mode)
{
    conv_body(src, dst, mode, blockIdx.x * blockDim.x + threadIdx.x);
}
__global__ __launch_bounds__(256) void convert_w4(
    const float* __restrict__ W0, const float* __restrict__ W1,
    const float* __restrict__ W2, const float* __restrict__ W3,
    __nv_bfloat16* __restrict__ dst)
{
    int w = blockIdx.y;
    const float* src = (w == 0) ? W0 : (w == 1) ? W1 : (w == 2) ? W2 : W3;
    conv_body(src, dst + (size_t)w * 1024 * KCAT, 1, blockIdx.x * blockDim.x + threadIdx.x);
}

// =================== mma.sync bf16 GEMM (R12 proven config) ===================
// 128x128 tile, BK=32, 256 threads (8 warps in 4x2: each 32 rows x 64 cols).
#define BK    32
#define ASTR  40
#define NSTG  2

__global__ __launch_bounds__(256) void gemm_mma(
    const __nv_bfloat16* __restrict__ A, const __nv_bfloat16* __restrict__ W,
    int wbase, int mode, float* __restrict__ Cf,
    __nv_bfloat16* __restrict__ H0, __nv_bfloat16* __restrict__ L0,
    __nv_bfloat16* __restrict__ H1, __nv_bfloat16* __restrict__ L1,
    __nv_bfloat16* __restrict__ H2, __nv_bfloat16* __restrict__ L2)
{
    __shared__ __nv_bfloat16 sA[NSTG][128 * ASTR];
    __shared__ __nv_bfloat16 sB[NSTG][128 * ASTR];

    const int z  = blockIdx.z;
    const int m0 = blockIdx.y * 128;
    const int n0 = blockIdx.x * 128;
    const int wrow0 = wbase + z * 1024 + n0;

    const int t    = threadIdx.x;
    const int lane = t & 31;
    const int wid  = t >> 5;
    const int wm   = wid & 3;
    const int wn   = wid >> 2;

    const uint32_t sAb = smem_u32(sA);
    const uint32_t sBb = smem_u32(sB);

    const int r0c = t >> 2, c0c = (t & 3) * 8;
    const int r1c = (t + 256) >> 2, c1c = ((t + 256) & 3) * 8;

    float acc[2][8][4];
#pragma unroll
    for (int mt = 0; mt < 2; mt++)
#pragma unroll
        for (int nt = 0; nt < 8; nt++)
#pragma unroll
            for (int q = 0; q < 4; q++) acc[mt][nt][q] = 0.f;

    const int nk = KCAT / BK;

    {
        cp16(sAb + (uint32_t)(r0c * ASTR + c0c) * 2, A + (size_t)(m0 + r0c) * KCAT + c0c);
        cp16(sBb + (uint32_t)(r0c * ASTR + c0c) * 2, W + (size_t)(wrow0 + r0c) * KCAT + c0c);
        cp16(sAb + (uint32_t)(r1c * ASTR + c1c) * 2, A + (size_t)(m0 + r1c) * KCAT + c1c);
        cp16(sBb + (uint32_t)(r1c * ASTR + c1c) * 2, W + (size_t)(wrow0 + r1c) * KCAT + c1c);
        asm volatile("cp.async.commit_group;" ::: "memory");
    }

    for (int k = 0; k < nk; k++) {
        const int s = k & 1;
        if (k + 1 < nk) {
            const int sn = (k + 1) & 1;
            const int kof = (k + 1) * BK;
            const uint32_t so = (uint32_t)(sn * 128 * ASTR) * 2;
            cp16(sAb + so + (uint32_t)(r0c * ASTR + c0c) * 2, A + (size_t)(m0 + r0c) * KCAT + kof + c0c);
            cp16(sBb + so + (uint32_t)(r0c * ASTR + c0c) * 2, W + (size_t)(wrow0 + r0c) * KCAT + kof + c0c);
            cp16(sAb + so + (uint32_t)(r1c * ASTR + c1c) * 2, A + (size_t)(m0 + r1c) * KCAT + kof + c1c);
            cp16(sBb + so + (uint32_t)(r1c * ASTR + c1c) * 2, W + (size_t)(wrow0 + r1c) * KCAT + kof + c1c);
            asm volatile("cp.async.commit_group;" ::: "memory");
            asm volatile("cp.async.wait_group 1;" ::: "memory");
        } else {
            asm volatile("cp.async.wait_group 0;" ::: "memory");
        }
        __syncthreads();

        const uint32_t sbase = (uint32_t)(s * 128 * ASTR) * 2;
#pragma unroll
        for (int kk = 0; kk < BK; kk += 16) {
            uint32_t af[2][4];
#pragma unroll
            for (int mt = 0; mt < 2; mt++) {
                int row = wm * 32 + mt * 16 + (lane & 15);
                int col = kk + (lane >> 4) * 8;
                ldm_x4(af[mt], sAb + sbase + (uint32_t)(row * ASTR + col) * 2);
            }
            uint32_t bf[8][2];
#pragma unroll
            for (int np = 0; np < 4; np++) {
                int nrow = wn * 64 + np * 16 + ((lane >> 4) << 3) + (lane & 7);
                int kcol = kk + ((lane >> 3) & 1) * 8;
                uint32_t r[4];
                ldm_x4(r, sBb + sbase + (uint32_t)(nrow * ASTR + kcol) * 2);
                bf[np * 2 + 0][0] = r[0]; bf[np * 2 + 0][1] = r[1];
                bf[np * 2 + 1][0] = r[2]; bf[np * 2 + 1][1] = r[3];
            }
#pragma unroll
            for (int mt = 0; mt < 2; mt++)
#pragma unroll
                for (int nt = 0; nt < 8; nt++)
                    mma16816(acc[mt][nt], af[mt], bf[nt]);
        }
        __syncthreads();
    }

    if (mode == 0) {
#pragma unroll
        for (int mt = 0; mt < 2; mt++) {
            int row = m0 + wm * 32 + mt * 16 + (lane >> 2);
#pragma unroll
            for (int nt = 0; nt < 8; nt++) {
                int col = n0 + wn * 64 + nt * 8 + (lane & 3) * 2;
                *(float2*)&Cf[(size_t)row * 1024 + col]       = make_float2(acc[mt][nt][0], acc[mt][nt][1]);
                *(float2*)&Cf[(size_t)(row + 8) * 1024 + col] = make_float2(acc[mt][nt][2], acc[mt][nt][3]);
            }
        }
    } else {
        __nv_bfloat16* Ch = (z == 0) ? H0 : (z == 1) ? H1 : H2;
        __nv_bfloat16* Cl = (z == 0) ? L0 : (z == 1) ? L1 : L2;
        const float sc = (z == 0) ? 0.125f : 1.0f;   // fold 1/sqrt(Hd) into Q
#pragma unroll
        for (int mt = 0; mt < 2; mt++) {
            int row = m0 + wm * 32 + mt * 16 + (lane >> 2);
#pragma unroll
            for (int nt = 0; nt < 8; nt++) {
                int col = n0 + wn * 64 + nt * 8 + (lane & 3) * 2;
                uint32_t hp, lp;
                split2(acc[mt][nt][0] * sc, acc[mt][nt][1] * sc, hp, lp);
                *(uint32_t*)&Ch[(size_t)row * 1024 + col] = hp;
                *(uint32_t*)&Cl[(size_t)row * 1024 + col] = lp;
                split2(acc[mt][nt][2] * sc, acc[mt][nt][3] * sc, hp, lp);
                *(uint32_t*)&Ch[(size_t)(row + 8) * 1024 + col] = hp;
                *(uint32_t*)&Cl[(size_t)(row + 8) * 1024 + col] = lp;
            }
        }
    }
}

// =================== Flash attention v3b: Q region aliased with K/V stage 1 ===================
// Block: 128 q-rows x 64 k-tile, 256 threads = 8 warps (m16 each).
// Q fragments hoisted to registers BEFORE stage 1 is ever written -> Q smem aliases stage 1.
// Smem: [stage0 36864B][stage1 = Q area 36864B] = 73728B -> 2 CTAs/SM (regs capped at 128).
#define FSTR3 72
#define STG_ELEMS (4 * 64 * FSTR3)                 // 18432 elems = 36864 B
#define ST_OFF(s) ((s) * STG_ELEMS)
#define QH_OFF (STG_ELEMS)                         // aliases stage 1 (KH+KL)
#define QL_OFF (STG_ELEMS + 128 * FSTR3)           // aliases stage 1 (VH+VL)
#define KH_OFF 0
#define KL_OFF (64 * FSTR3)
#define VH_OFF (2 * 64 * FSTR3)
#define VL_OFF (3 * 64 * FSTR3)
#define FLASH3_SMEM (2 * STG_ELEMS * 2)            // 73728 B

__global__ __launch_bounds__(256, 2) void flash_fwd3(
    const __nv_bfloat16* __restrict__ Qh, const __nv_bfloat16* __restrict__ Ql,
    const __nv_bfloat16* __restrict__ Kh, const __nv_bfloat16* __restrict__ Kl,
    const __nv_bfloat16* __restrict__ Vh, const __nv_bfloat16* __restrict__ Vl,
    __nv_bfloat16* __restrict__ Ocat, const int* __restrict__ causalp, int S)
{
    extern __shared__ __nv_bfloat16 smem3[];
    const uint32_t sb = smem_u32(smem3);

    const int qt = gridDim.x - 1 - blockIdx.x;   // heavy (large-qt) blocks first
    const int h  = blockIdx.y;
    const int b  = blockIdx.z;
    const int t  = threadIdx.x;
    const int lane = t & 31;
    const int wid  = t >> 5;
    const int wq   = wid * 16;
    const int causal = causalp[0];

    const int q0 = qt * 128;
    const size_t tok0 = (size_t)b * S;
    const size_t colh = (size_t)h * HDIM;

    // ---- prologue: Q tiles (own commit group, into stage-1 area), then k-tile 0 ----
#pragma unroll
    for (int c = 0; c < 4; c++) {
        int ci = t + 256 * c;            // 0..1023 chunks of 8 bf16
        int row = ci >> 3, col8 = (ci & 7) * 8;
        const __nv_bfloat16* gq = Qh + (tok0 + q0 + row) * D_MODEL + colh + col8;
        const __nv_bfloat16* gl = Ql + (tok0 + q0 + row) * D_MODEL + colh + col8;
        cp16(sb + (uint32_t)(QH_OFF + row * FSTR3 + col8) * 2, gq);
        cp16(sb + (uint32_t)(QL_OFF + row * FSTR3 + col8) * 2, gl);
    }
    asm volatile("cp.async.commit_group;" ::: "memory");
    const int ntot = S >> 6;
    const int nkt  = causal ? min(ntot, 2 * qt + 2) : ntot;
    {
#pragma unroll
        for (int c = 0; c < 2; c++) {
            int ci = t + 256 * c;        // 0..511
            int row = ci >> 3, col8 = (ci & 7) * 8;
            size_t g = (tok0 + row) * D_MODEL + colh + col8;
            uint32_t d = (uint32_t)(ST_OFF(0) + row * FSTR3 + col8) * 2;
            cp16(sb + d + KH_OFF * 2, Kh + g);
            cp16(sb + d + KL_OFF * 2, Kl + g);
            cp16(sb + d + VH_OFF * 2, Vh + g);
            cp16(sb + d + VL_OFF * 2, Vl + g);
        }
        asm volatile("cp.async.commit_group;" ::: "memory");
    }

    // ---- Q fragments: register-resident for the whole k-loop ----
    asm volatile("cp.async.wait_group 1;" ::: "memory");   // Q group complete
    __syncthreads();
    uint32_t qfh[4][4], qfl[4][4];
#pragma unroll
    for (int kk4 = 0; kk4 < 4; kk4++) {
        int row = wq + (lane & 15);
        int col = kk4 * 16 + (lane >> 4) * 8;
        ldm_x4(qfh[kk4], sb + (uint32_t)(QH_OFF + row * FSTR3 + col) * 2);
        ldm_x4(qfl[kk4], sb + (uint32_t)(QL_OFF + row * FSTR3 + col) * 2);
    }
    __syncthreads();   // all warps done reading Q before anyone overwrites stage-1/Q area

    float sacc[8][4], oacc[8][4];
#pragma unroll
    for (int nt = 0; nt < 8; nt++)
#pragma unroll
        for (int q = 0; q < 4; q++) oacc[nt][q] = 0.f;
    float mrun0 = -CUDART_INF_F, mrun1 = -CUDART_INF_F, lrun0 = 0.f, lrun1 = 0.f;

    for (int kt = 0; kt < nkt; kt++) {
        const int s  = kt & 1;
        const int k0 = kt * 64;
        if (kt + 1 < nkt) {
            const int sn = (kt + 1) & 1;
#pragma unroll
            for (int c = 0; c < 2; c++) {
                int ci = t + 256 * c;
                int row = ci >> 3, col8 = (ci & 7) * 8;
                size_t g = (tok0 + k0 + 64 + row) * D_MODEL + colh + col8;
                uint32_t d = (uint32_t)(ST_OFF(sn) + row * FSTR3 + col8) * 2;
                cp16(sb + d + KH_OFF * 2, Kh + g);
                cp16(sb + d + KL_OFF * 2, Kl + g);
                cp16(sb + d + VH_OFF * 2, Vh + g);
                cp16(sb + d + VL_OFF * 2, Vl + g);
            }
            asm volatile("cp.async.commit_group;" ::: "memory");
            asm volatile("cp.async.wait_group 1;" ::: "memory");
        } else {
            asm volatile("cp.async.wait_group 0;" ::: "memory");
        }
        __syncthreads();

        const uint32_t kbase = sb + (uint32_t)ST_OFF(s) * 2;

        // ---- S = Q K^T (3-term split), per warp 16q x 64k ----
#pragma unroll
        for (int nt = 0; nt < 8; nt++)
#pragma unroll
            for (int q = 0; q < 4; q++) sacc[nt][q] = 0.f;

#pragma unroll
        for (int kk4 = 0; kk4 < 4; kk4++) {
            const int kk = kk4 * 16;
            uint32_t bh[8][2], bl[8][2];
#pragma unroll
            for (int np = 0; np < 4; np++) {
                int nrow = np * 16 + ((lane >> 4) << 3) + (lane & 7);
                int kcol = kk + ((lane >> 3) & 1) * 8;
                uint32_t r[4];
                ldm_x4(r, kbase + (uint32_t)(KH_OFF + nrow * FSTR3 + kcol) * 2);
                bh[np * 2 + 0][0] = r[0]; bh[np * 2 + 0][1] = r[1];
                bh[np * 2 + 1][0] = r[2]; bh[np * 2 + 1][1] = r[3];
                ldm_x4(r, kbase + (uint32_t)(KL_OFF + nrow * FSTR3 + kcol) * 2);
                bl[np * 2 + 0][0] = r[0]; bl[np * 2 + 0][1] = r[1];
                bl[np * 2 + 1][0] = r[2]; bl[np * 2 + 1][1] = r[3];
            }
#pragma unroll
            for (int nt = 0; nt < 8; nt++) {
                mma16816(sacc[nt], qfh[kk4], bh[nt]);
                mma16816(sacc[nt], qfh[kk4], bl[nt]);
                mma16816(sacc[nt], qfl[kk4], bh[nt]);
            }
        }

        // ---- causal mask ----
        if (causal && (k0 + 63 > q0 + wq)) {
            int qg0 = q0 + wq + (lane >> 2);
#pragma unroll
            for (int nt = 0; nt < 8; nt++) {
                int kg = k0 + nt * 8 + (lane & 3) * 2;
                if (kg     > qg0)     sacc[nt][0] = -CUDART_INF_F;
                if (kg + 1 > qg0)     sacc[nt][1] = -CUDART_INF_F;
                if (kg     > qg0 + 8) sacc[nt][2] = -CUDART_INF_F;
                if (kg + 1 > qg0 + 8) sacc[nt][3] = -CUDART_INF_F;
            }
        }

        // ---- online softmax ----
        {
            float m0 = sacc[0][0], m1 = sacc[0][2];
#pragma unroll
            for (int nt = 0; nt < 8; nt++) {
                m0 = fmaxf(m0, fmaxf(sacc[nt][0], sacc[nt][1]));
                m1 = fmaxf(m1, fmaxf(sacc[nt][2], sacc[nt][3]));
            }
            m0 = fmaxf(m0, __shfl_xor_sync(0xffffffffu, m0, 1));
            m0 = fmaxf(m0, __shfl_xor_sync(0xffffffffu, m0, 2));
            m1 = fmaxf(m1, __shfl_xor_sync(0xffffffffu, m1, 1));
            m1 = fmaxf(m1, __shfl_xor_sync(0xffffffffu, m1, 2));
            float mn0 = fmaxf(mrun0, m0), mn1 = fmaxf(mrun1, m1);
            float cr0 = __expf(mrun0 - mn0), cr1 = __expf(mrun1 - mn1);
            float ls0 = 0.f, ls1 = 0.f;
#pragma unroll
            for (int nt = 0; nt < 8; nt++) {
                sacc[nt][0] = __expf(sacc[nt][0] - mn0);
                sacc[nt][1] = __expf(sacc[nt][1] - mn0);
                sacc[nt][2] = __expf(sacc[nt][2] - mn1);
                sacc[nt][3] = __expf(sacc[nt][3] - mn1);
                ls0 += sacc[nt][0] + sacc[nt][1];
                ls1 += sacc[nt][2] + sacc[nt][3];
            }
            ls0 += __shfl_xor_sync(0xffffffffu, ls0, 1);
            ls0 += __shfl_xor_sync(0xffffffffu, ls0, 2);
            ls1 += __shfl_xor_sync(0xffffffffu, ls1, 1);
            ls1 += __shfl_xor_sync(0xffffffffu, ls1, 2);
            lrun0 = lrun0 * cr0 + ls0;  mrun0 = mn0;
            lrun1 = lrun1 * cr1 + ls1;  mrun1 = mn1;
#pragma unroll
            for (int nt = 0; nt < 8; nt++) {
                oacc[nt][0] *= cr0; oacc[nt][1] *= cr0;
                oacc[nt][2] *= cr1; oacc[nt][3] *= cr1;
            }
        }

        // ---- O += P V (3-term split); P frags direct from sacc ----
#pragma unroll
        for (int jt = 0; jt < 4; jt++) {
            uint32_t aPh[4], aPl[4];
            split2(sacc[2 * jt][0],     sacc[2 * jt][1],     aPh[0], aPl[0]);
            split2(sacc[2 * jt][2],     sacc[2 * jt][3],     aPh[1], aPl[1]);
            split2(sacc[2 * jt + 1][0], sacc[2 * jt + 1][1], aPh[2], aPl[2]);
            split2(sacc[2 * jt + 1][2], sacc[2 * jt + 1][3], aPh[3], aPl[3]);

            uint32_t vh[8][2], vl[8][2];
#pragma unroll
            for (int dp = 0; dp < 4; dp++) {
                int vrow = jt * 16 + (lane & 15);
                int vcol = dp * 16 + (lane >> 4) * 8;
                uint32_t r[4];
                ldm_x4_t(r, kbase + (uint32_t)(VH_OFF + vrow * FSTR3 + vcol) * 2);
                vh[dp * 2 + 0][0] = r[0]; vh[dp * 2 + 0][1] = r[1];
                vh[dp * 2 + 1][0] = r[2]; vh[dp * 2 + 1][1] = r[3];
                ldm_x4_t(r, kbase + (uint32_t)(VL_OFF + vrow * FSTR3 + vcol) * 2);
                vl[dp * 2 + 0][0] = r[0]; vl[dp * 2 + 0][1] = r[1];
                vl[dp * 2 + 1][0] = r[2]; vl[dp * 2 + 1][1] = r[3];
            }
#pragma unroll
            for (int nt = 0; nt < 8; nt++) {
                mma16816(oacc[nt], aPh, vh[nt]);
                mma16816(oacc[nt], aPh, vl[nt]);
                mma16816(oacc[nt], aPl, vh[nt]);
            }
        }
        __syncthreads();
    }

    // ---- epilogue: normalize, write split-cat [hi,hi,lo] into Ocat ----
    {
        float inv0 = 1.f / lrun0, inv1 = 1.f / lrun1;
        size_t r0 = tok0 + q0 + wq + (lane >> 2);
        size_t r1 = r0 + 8;
#pragma unroll
        for (int nt = 0; nt < 8; nt++) {
            size_t col = colh + nt * 8 + (lane & 3) * 2;
            uint32_t hp, lp;
            split2(oacc[nt][0] * inv0, oacc[nt][1] * inv0, hp, lp);
            *(uint32_t*)&Ocat[r0 * KCAT + col]        = hp;
            *(uint32_t*)&Ocat[r0 * KCAT + col + 1024] = hp;
            *(uint32_t*)&Ocat[r0 * KCAT + col + 2048] = lp;
            split2(oacc[nt][2] * inv1, oacc[nt][3] * inv1, hp, lp);
            *(uint32_t*)&Ocat[r1 * KCAT + col]        = hp;
            *(uint32_t*)&Ocat[r1 * KCAT + col + 1024] = hp;
            *(uint32_t*)&Ocat[r1 * KCAT + col + 2048] = lp;
        }
    }
}

// ---------------- launch ----------------
extern "C" void kernel_launch(void* const* d_in, const int* in_sizes, int n_in,
                              void* d_out, int out_size)
{
    const float* x  = (const float*)d_in[0];
    const float* Wq = (const float*)d_in[1];
    const float* Wk = (const float*)d_in[2];
    const float* Wv = (const float*)d_in[3];
    const float* Wo = (const float*)d_in[4];
    const int*   causal = (const int*)d_in[5];

    const int BS = in_sizes[0] / D_MODEL;   // 4096
    const int S  = 2048;
    const int B  = BS / S;

    __nv_bfloat16 *xcat, *wcat, *ocat, *qh, *ql, *kh, *kl, *vh, *vl;
    cudaGetSymbolAddress((void**)&xcat, g_Xcat);
    cudaGetSymbolAddress((void**)&wcat, g_Wcat);
    cudaGetSymbolAddress((void**)&ocat, g_Ocat);
    cudaGetSymbolAddress((void**)&qh, g_Qh);  cudaGetSymbolAddress((void**)&ql, g_Ql);
    cudaGetSymbolAddress((void**)&kh, g_Kh);  cudaGetSymbolAddress((void**)&kl, g_Kl);
    cudaGetSymbolAddress((void**)&vh, g_Vh);  cudaGetSymbolAddress((void**)&vl, g_Vl);

    cudaFuncSetAttribute(flash_fwd3, cudaFuncAttributeMaxDynamicSharedMemorySize, FLASH3_SMEM);

    // ---- convert x and all four weights to bf16 split-cat ----
    convert_split<<<(BS * 256) / 256, 256>>>(x, xcat, 0);
    convert_w4<<<dim3(1024, 4), 256>>>(Wq, Wk, Wv, Wo, wcat);

    // ---- Q/K/V projections -> bf16 hi/lo split outputs (Q pre-scaled by 0.125) ----
    gemm_mma<<<dim3(D_MODEL / 128, BS / 128, 3), 256>>>(
        xcat, wcat, 0, 1, nullptr, qh, ql, kh, kl, vh, vl);

    // ---- tensor-core flash attention -> Ocat (split-cat) ----
    dim3 gfl(S / 128, NHEAD, B);
    flash_fwd3<<<gfl, 256, FLASH3_SMEM>>>(qh, ql, kh, kl, vh, vl, ocat, causal, S);

    // ---- output projection -> fp32 d_out ----
    gemm_mma<<<dim3(D_MODEL / 128, BS / 128, 1), 256>>>(
        ocat, wcat, 3 * 1024, 0, (float*)d_out,
        nullptr, nullptr, nullptr, nullptr, nullptr, nullptr);
}